// round 6
// baseline (speedup 1.0000x reference)
#include <cuda_runtime.h>
#include <cuda_bf16.h>

// Brick (tiled) gather formulation, v5.
//   grid_build: g_grid[cell] = row+1 (0 empty; static zero-init valid).
//   brick_conv: one block per 8x4x4 interior brick with 10x6x6 halo.
//     Phase A: probe halo occupancy into socc[], build per-interior-cell
//              27-bit neighbor masks + compact list of occupied centers,
//              load occupied halo feats rows into dense smem (46 KB).
//     Phase B: for each occupied center, walk its mask with __ffs and
//              accumulate taps from smem; one 128B store per output.
//   grid_clear: zero only the N occupied cells.
// Feats are read from L2 once per halo appearance (~2.8x) instead of once
// per edge (~8.1x): ~112 MB instead of ~311 MB.

#define LGRID 100
#define NCELLS (LGRID * LGRID * LGRID)
#define BXI 8
#define BYI 4
#define BZI 4
#define HXD 10
#define HYD 6
#define HZD 6
#define NHALO (HXD * HYD * HZD)   // 360
#define NINT  (BXI * BYI * BZI)   // 128
#define TPB 256

__device__ int g_grid[NCELLS];    // cell -> row+1, 0 = empty

// d = dx*36 + dy*6 + dz for k = ((dx+1)*3+(dy+1))*3+(dz+1)
__constant__ int c_koff[27] = {
    -43, -42, -41, -37, -36, -35, -31, -30, -29,
     -7,  -6,  -5,  -1,   0,   1,   5,   6,   7,
     29,  30,  31,  35,  36,  37,  41,  42,  43
};

__global__ void grid_build_kernel(const int* __restrict__ coords, int N) {
    int i = blockIdx.x * blockDim.x + threadIdx.x;
    if (i >= N) return;
    int x = coords[3 * i + 0], y = coords[3 * i + 1], z = coords[3 * i + 2];
    g_grid[(x * LGRID + y) * LGRID + z] = i + 1;
}

__global__ void grid_clear_kernel(const int* __restrict__ coords, int N) {
    int i = blockIdx.x * blockDim.x + threadIdx.x;
    if (i >= N) return;
    int x = coords[3 * i + 0], y = coords[3 * i + 1], z = coords[3 * i + 2];
    g_grid[(x * LGRID + y) * LGRID + z] = 0;
}

__global__ __launch_bounds__(TPB, 4)
void brick_conv_kernel(const float4* __restrict__ feats,   // [N, 8] float4
                       const float4* __restrict__ kern,    // [27, 8] float4
                       float4* __restrict__ out)           // [N, 8] float4
{
    __shared__ float4 sfeats[NHALO * 8];   // 46080 B
    __shared__ int    socc[NHALO];         //  1440 B
    __shared__ int    smask[NINT];         //   512 B
    __shared__ int    slist[NINT];         //   512 B  (packed hc | ic<<9)
    __shared__ int    scnt;

    int tid = threadIdx.x;
    if (tid == 0) scnt = 0;

    int gx0 = (int)blockIdx.x * BXI - 1;
    int gy0 = (int)blockIdx.y * BYI - 1;
    int gz0 = (int)blockIdx.z * BZI - 1;

    // ---- Phase A1: probe halo occupancy ----
#pragma unroll
    for (int c = tid; c < NHALO; c += TPB) {
        int hz = c % HZD;
        int t  = c / HZD;
        int hy = t % HYD;
        int hx = t / HYD;
        int gx = gx0 + hx, gy = gy0 + hy, gz = gz0 + hz;
        int enc = 0;
        if (((unsigned)gx < LGRID) & ((unsigned)gy < LGRID) & ((unsigned)gz < LGRID))
            enc = g_grid[(gx * LGRID + gy) * LGRID + gz];
        socc[c] = enc;
    }
    __syncthreads();

    // ---- Phase A2: masks + compact list of occupied interior cells ----
    if (tid < NINT) {
        int iz = tid & 3, iy = (tid >> 2) & 3, ix = tid >> 4;
        int hc = (ix + 1) * (HYD * HZD) + (iy + 1) * HZD + (iz + 1);
        if (socc[hc] > 0) {
            int m = 0;
#pragma unroll
            for (int k = 0; k < 27; k++)
                m |= (socc[hc + c_koff[k]] > 0) << k;
            smask[tid] = m;
            int pos = atomicAdd(&scnt, 1);
            slist[pos] = hc | (tid << 9);
        }
    }

    // ---- Phase A3: load occupied halo rows into smem ----
    for (int p = tid; p < NHALO * 8; p += TPB) {
        int c = p >> 3, g = p & 7;
        int enc = socc[c];
        if (enc > 0) sfeats[p] = feats[(long long)(enc - 1) * 8 + g];
    }
    __syncthreads();

    // ---- Phase B: compute occupied centers ----
    int cnt = scnt;
    int total = cnt * 8;
    for (int p = tid; p < total; p += TPB) {
        int packed = slist[p >> 3];
        int g  = p & 7;
        int hc = packed & 511;
        int ic = packed >> 9;
        int m  = smask[ic];
        int row = socc[hc] - 1;

        float4 acc = make_float4(0.f, 0.f, 0.f, 0.f);
        while (m) {
            int k = __ffs(m) - 1;
            m &= m - 1;
            int d = c_koff[k];
            float4 f = sfeats[(hc + d) * 8 + g];
            float4 w = __ldg(&kern[k * 8 + g]);
            acc.x = fmaf(f.x, w.x, acc.x);
            acc.y = fmaf(f.y, w.y, acc.y);
            acc.z = fmaf(f.z, w.z, acc.z);
            acc.w = fmaf(f.w, w.w, acc.w);
        }
        out[(long long)row * 8 + g] = acc;
    }
}

extern "C" void kernel_launch(void* const* d_in, const int* in_sizes, int n_in,
                              void* d_out, int out_size) {
    const int*    coords = (const int*)d_in[0];
    const float4* feats  = (const float4*)d_in[3];
    const float4* kern   = (const float4*)d_in[4];
    float4*       out    = (float4*)d_out;

    int N = out_size / 32;

    {
        int threads = 256;
        int blocks = (N + threads - 1) / threads;
        grid_build_kernel<<<blocks, threads>>>(coords, N);
    }
    {
        dim3 grid((LGRID + BXI - 1) / BXI,   // 13
                  (LGRID + BYI - 1) / BYI,   // 25
                  (LGRID + BZI - 1) / BZI);  // 25
        brick_conv_kernel<<<grid, TPB>>>(feats, kern, out);
    }
    {
        int threads = 256;
        int blocks = (N + threads - 1) / threads;
        grid_clear_kernel<<<blocks, threads>>>(coords, N);
    }
}

// round 7
// speedup vs baseline: 1.4131x; 1.4131x over previous
#include <cuda_runtime.h>
#include <cuda_bf16.h>

// Compact-halo brick gather, v6.
//   grid_build: g_grid[cell] = row+1 (0 empty; static zero-init valid).
//   brick_conv: one block per 8x4x4 interior brick with 10x6x6 halo.
//     A1: probe halo; occupied cells get compact slots (shared counter);
//         socc[hc] = slot+1, or -(row+1) on overflow (>CAP, ~never), or 0.
//     A2: per-interior-cell 27-bit neighbor masks + compact center list.
//     A3: dense coalesced load of the ~108 occupied halo rows into smem.
//     B : per occupied center, __ffs mask walk over smem taps, one store.
//   grid_clear: zero only the N occupied cells.
// Feats L2 traffic ~112 MB (halo factor 2.8) vs ~311 MB for flat gather;
// ~28 KB smem -> 8 blocks/SM (R6 was 46 KB -> 4).

#define LGRID 100
#define NCELLS (LGRID * LGRID * LGRID)
#define BXI 8
#define BYI 4
#define BZI 4
#define HXD 10
#define HYD 6
#define HZD 6
#define NHALO (HXD * HYD * HZD)   // 360
#define NINT  (BXI * BYI * BZI)   // 128
#define TPB 256
#define CAP 176                   // compact feats slots (mean occ ~108, +7.8 sigma)

__device__ int g_grid[NCELLS];    // cell -> row+1, 0 = empty

// d = dx*36 + dy*6 + dz for k = ((dx+1)*3+(dy+1))*3+(dz+1)
__constant__ int c_koff[27] = {
    -43, -42, -41, -37, -36, -35, -31, -30, -29,
     -7,  -6,  -5,  -1,   0,   1,   5,   6,   7,
     29,  30,  31,  35,  36,  37,  41,  42,  43
};

__global__ void grid_build_kernel(const int* __restrict__ coords, int N) {
    int i = blockIdx.x * blockDim.x + threadIdx.x;
    if (i >= N) return;
    int x = coords[3 * i + 0], y = coords[3 * i + 1], z = coords[3 * i + 2];
    g_grid[(x * LGRID + y) * LGRID + z] = i + 1;
}

__global__ void grid_clear_kernel(const int* __restrict__ coords, int N) {
    int i = blockIdx.x * blockDim.x + threadIdx.x;
    if (i >= N) return;
    int x = coords[3 * i + 0], y = coords[3 * i + 1], z = coords[3 * i + 2];
    g_grid[(x * LGRID + y) * LGRID + z] = 0;
}

__global__ __launch_bounds__(TPB)
void brick_conv_kernel(const float4* __restrict__ feats,   // [N, 8] float4
                       const float4* __restrict__ kern,    // [27, 8] float4
                       float4* __restrict__ out)           // [N, 8] float4
{
    __shared__ float4 sfeats[CAP * 8];     // 22528 B
    __shared__ int    socc[NHALO];         //  1440 B  slot+1 / -(row+1) / 0
    __shared__ int    srow[CAP];           //   704 B  slot -> feats row
    __shared__ int    smask[NINT];         //   512 B
    __shared__ int    slist[NINT];         //   512 B  hc | ic<<9
    __shared__ int    shcnt, scnt;

    int tid = threadIdx.x;
    if (tid == 0) { shcnt = 0; scnt = 0; }
    __syncthreads();

    int gx0 = (int)blockIdx.x * BXI - 1;
    int gy0 = (int)blockIdx.y * BYI - 1;
    int gz0 = (int)blockIdx.z * BZI - 1;

    // ---- A1: probe halo, assign compact slots ----
#pragma unroll
    for (int c = tid; c < NHALO; c += TPB) {
        int hz = c % HZD;
        int t  = c / HZD;
        int hy = t % HYD;
        int hx = t / HYD;
        int gx = gx0 + hx, gy = gy0 + hy, gz = gz0 + hz;
        int enc = 0;
        if (((unsigned)gx < LGRID) & ((unsigned)gy < LGRID) & ((unsigned)gz < LGRID))
            enc = g_grid[(gx * LGRID + gy) * LGRID + gz];
        int v = 0;
        if (enc > 0) {
            int slot = atomicAdd(&shcnt, 1);
            if (slot < CAP) { srow[slot] = enc - 1; v = slot + 1; }
            else            { v = -enc; }              // global fallback
        }
        socc[c] = v;
    }
    __syncthreads();

    int nslots = min(shcnt, CAP);

    // ---- A2: neighbor masks + compact center list ----
    if (tid < NINT) {
        int iz = tid & 3, iy = (tid >> 2) & 3, ix = tid >> 4;
        int hc = (ix + 1) * (HYD * HZD) + (iy + 1) * HZD + (iz + 1);
        if (socc[hc] != 0) {
            int m = 0;
#pragma unroll
            for (int k = 0; k < 27; k++)
                m |= (socc[hc + c_koff[k]] != 0) << k;
            smask[tid] = m;
            int pos = atomicAdd(&scnt, 1);
            slist[pos] = hc | (tid << 9);
        }
    }

    // ---- A3: dense coalesced feats load into compact smem ----
    for (int p = tid; p < nslots * 8; p += TPB) {
        int slot = p >> 3, g = p & 7;
        sfeats[p] = feats[(long long)srow[slot] * 8 + g];
    }
    __syncthreads();

    // ---- B: compute occupied centers ----
    int cnt = scnt;
    for (int p = tid; p < cnt * 8; p += TPB) {
        int packed = slist[p >> 3];
        int g  = p & 7;
        int hc = packed & 511;
        int ic = packed >> 9;
        int m  = smask[ic];
        int cid = socc[hc];
        int row = (cid > 0) ? srow[cid - 1] : (-cid - 1);

        float4 acc = make_float4(0.f, 0.f, 0.f, 0.f);
        while (m) {
            int k = __ffs(m) - 1;
            m &= m - 1;
            int id = socc[hc + c_koff[k]];
            float4 f;
            if (id > 0) f = sfeats[(id - 1) * 8 + g];
            else        f = feats[(long long)(-id - 1) * 8 + g];
            float4 w = __ldg(&kern[k * 8 + g]);
            acc.x = fmaf(f.x, w.x, acc.x);
            acc.y = fmaf(f.y, w.y, acc.y);
            acc.z = fmaf(f.z, w.z, acc.z);
            acc.w = fmaf(f.w, w.w, acc.w);
        }
        out[(long long)row * 8 + g] = acc;
    }
}

extern "C" void kernel_launch(void* const* d_in, const int* in_sizes, int n_in,
                              void* d_out, int out_size) {
    const int*    coords = (const int*)d_in[0];
    const float4* feats  = (const float4*)d_in[3];
    const float4* kern   = (const float4*)d_in[4];
    float4*       out    = (float4*)d_out;

    int N = out_size / 32;

    {
        int threads = 256;
        int blocks = (N + threads - 1) / threads;
        grid_build_kernel<<<blocks, threads>>>(coords, N);
    }
    {
        dim3 grid((LGRID + BXI - 1) / BXI,   // 13
                  (LGRID + BYI - 1) / BYI,   // 25
                  (LGRID + BZI - 1) / BZI);  // 25
        brick_conv_kernel<<<grid, TPB>>>(feats, kern, out);
    }
    {
        int threads = 256;
        int blocks = (N + threads - 1) / threads;
        grid_clear_kernel<<<blocks, threads>>>(coords, N);
    }
}